// round 1
// baseline (speedup 1.0000x reference)
#include <cuda_runtime.h>

// shuffleAug: per-sample dihedral transform of two (B,64,128,128) fp32 tensors.
// The 5 chained gathers (flipX f0, flipY f1, swap f2, flipX f3, flipY f4)
// compose to a single source-index map:
//   if f2 (swap):  src_i = flip_{f0^f4}(j), src_j = flip_{f1^f3}(i)
//   else:          src_i = flip_{f0^f3}(i), src_j = flip_{f1^f4}(j)
// Channel layout is untouched, so out1 = T(x1), out2 = T(x2).
//
// Coalescing: each block produces one 32x32 output tile of one (b,c) plane.
// The corresponding source region is a contiguous 32x32 tile (possibly
// reversed/transposed). We load it coalesced into a padded smem tile and
// write the output coalesced, doing the permutation in smem.

#define HH 128
#define HWSZ (128 * 128)

__global__ void __launch_bounds__(256) shuffleAug_kernel(
    const float* __restrict__ x1,
    const float* __restrict__ x2,
    const int* __restrict__ fb,   // (5, B) int32
    float* __restrict__ out,
    int B)
{
    __shared__ float tile[32][33];  // +1 pad: conflict-free column reads in swap case

    const int plane = blockIdx.z;       // b * 128 + c  (c in [0,128) over concat channels)
    const int b = plane >> 7;
    const int c = plane & 127;

    const int f0 = fb[0 * B + b];
    const int f1 = fb[1 * B + b];
    const int f2 = fb[2 * B + b];
    const int f3 = fb[3 * B + b];
    const int f4 = fb[4 * B + b];

    const int sw = f2;
    const int fi = sw ? (f0 ^ f4) : (f0 ^ f3);
    const int fj = sw ? (f1 ^ f3) : (f1 ^ f4);

    const float* src;
    float* dst;
    if (c < 64) {
        src = x1 + ((size_t)b * 64 + c) * HWSZ;
        dst = out + ((size_t)b * 64 + c) * HWSZ;
    } else {
        src = x2 + ((size_t)b * 64 + (c - 64)) * HWSZ;
        dst = out + (size_t)B * 64 * HWSZ + ((size_t)b * 64 + (c - 64)) * HWSZ;
    }

    const int i0 = blockIdx.y * 32;     // output tile origin
    const int j0 = blockIdx.x * 32;

    // Source tile origin: u is the pre-flip coordinate feeding src_i, v feeds src_j.
    const int u0 = sw ? j0 : i0;
    const int v0 = sw ? i0 : j0;
    const int si0 = fi ? (HH - 32) - u0 : u0;
    const int sj0 = fj ? (HH - 32) - v0 : v0;

    const int tx = threadIdx.x;         // 0..31
    const int ty = threadIdx.y;         // 0..7

    // Coalesced load of the 32x32 source tile.
    #pragma unroll
    for (int k = 0; k < 4; k++) {
        const int r = ty + k * 8;
        tile[r][tx] = src[(size_t)(si0 + r) * HH + (sj0 + tx)];
    }
    __syncthreads();

    // Coalesced store of the 32x32 output tile, permuting through smem.
    #pragma unroll
    for (int k = 0; k < 4; k++) {
        const int r = ty + k * 8;       // output row within tile
        const int ul = sw ? tx : r;     // local u coord
        const int vl = sw ? r : tx;     // local v coord
        const int lu = fi ? 31 - ul : ul;   // smem row  = src_i - si0
        const int lv = fj ? 31 - vl : vl;   // smem col  = src_j - sj0
        dst[(size_t)(i0 + r) * HH + (j0 + tx)] = tile[lu][lv];
    }
}

extern "C" void kernel_launch(void* const* d_in, const int* in_sizes, int n_in,
                              void* d_out, int out_size)
{
    const float* x1 = (const float*)d_in[0];
    const float* x2 = (const float*)d_in[1];
    const int* fb   = (const int*)d_in[2];
    float* out      = (float*)d_out;

    const int B = in_sizes[2] / 5;          // flip_bits is (5, B)

    dim3 block(32, 8, 1);
    dim3 grid(128 / 32, 128 / 32, B * 128); // 4 x 4 x 4096 = 65536 blocks

    shuffleAug_kernel<<<grid, block>>>(x1, x2, fb, out, B);
}

// round 2
// speedup vs baseline: 1.0643x; 1.0643x over previous
#include <cuda_runtime.h>

// shuffleAug: per-sample dihedral transform of two (B,64,128,128) fp32 tensors.
// Composition of the 5 gathers:
//   if f2 (swap):  src_i = flip_{f0^f4}(j), src_j = flip_{f1^f3}(i)
//   else:          src_i = flip_{f0^f3}(i), src_j = flip_{f1^f4}(j)
// out1 = T(x1), out2 = T(x2) independently (channels untouched).
//
// float4 everywhere. Non-swap: direct vectorized copy (row flip = mirrored
// aligned float4 load + component reversal), no smem. Swap: 32x32 tile
// transpose through padded smem (conflict-free both phases).

#define HH 128
#define HWSZ (128 * 128)

__global__ void __launch_bounds__(256) shuffleAug_kernel(
    const float* __restrict__ x1,
    const float* __restrict__ x2,
    const int* __restrict__ fb,   // (5, B) int32
    float* __restrict__ out,
    int B)
{
    __shared__ float tile[32][33];

    const int plane = blockIdx.z;       // b * 128 + c
    const int b = plane >> 7;
    const int c = plane & 127;

    const int f0 = fb[0 * B + b];
    const int f1 = fb[1 * B + b];
    const int sw = fb[2 * B + b];
    const int f3 = fb[3 * B + b];
    const int f4 = fb[4 * B + b];

    const int fi = sw ? (f0 ^ f4) : (f0 ^ f3);
    const int fj = sw ? (f1 ^ f3) : (f1 ^ f4);

    const float* src;
    float* dst;
    if (c < 64) {
        src = x1 + ((size_t)b * 64 + c) * HWSZ;
        dst = out + ((size_t)b * 64 + c) * HWSZ;
    } else {
        src = x2 + ((size_t)b * 64 + (c - 64)) * HWSZ;
        dst = out + (size_t)B * 64 * HWSZ + ((size_t)b * 64 + (c - 64)) * HWSZ;
    }

    const int i0 = blockIdx.y * 32;     // output tile origin
    const int j0 = blockIdx.x * 32;

    const int tid = threadIdx.x;        // 0..255
    const int lr  = tid >> 3;           // 0..31  output row within tile
    const int lg  = tid & 7;            // 0..7   float4 group within row

    if (!sw) {
        // ---- no transpose: one float4 per thread, no smem ----
        const int r  = i0 + lr;
        const int sr = fi ? (HH - 1) - r : r;
        float4 v;
        if (!fj) {
            v = *(const float4*)(src + (size_t)sr * HH + j0 + 4 * lg);
        } else {
            float4 t = *(const float4*)(src + (size_t)sr * HH + (HH - 4) - j0 - 4 * lg);
            v.x = t.w; v.y = t.z; v.z = t.y; v.w = t.x;
        }
        *(float4*)(dst + (size_t)r * HH + j0 + 4 * lg) = v;
    } else {
        // ---- transpose path through smem ----
        const int si0 = fi ? (HH - 32) - j0 : j0;   // source rows cover u = j
        const int sj0 = fj ? (HH - 32) - i0 : i0;   // source cols cover v = i

        // Coalesced float4 load of the source tile -> padded smem.
        {
            float4 t = *(const float4*)(src + (size_t)(si0 + lr) * HH + sj0 + 4 * lg);
            tile[lr][4 * lg + 0] = t.x;
            tile[lr][4 * lg + 1] = t.y;
            tile[lr][4 * lg + 2] = t.z;
            tile[lr][4 * lg + 3] = t.w;
        }
        __syncthreads();

        // out(i,j): smem row = fi ? 31-jl : jl, smem col = fj ? 31-il : il
        const int scol = fj ? 31 - lr : lr;
        float4 v;
        {
            const int jl0 = 4 * lg;
            const int r0 = fi ? 31 - jl0 : jl0;
            const int st = fi ? -1 : 1;
            v.x = tile[r0         ][scol];
            v.y = tile[r0 + st    ][scol];
            v.z = tile[r0 + 2 * st][scol];
            v.w = tile[r0 + 3 * st][scol];
        }
        *(float4*)(dst + (size_t)(i0 + lr) * HH + j0 + 4 * lg) = v;
    }
}

extern "C" void kernel_launch(void* const* d_in, const int* in_sizes, int n_in,
                              void* d_out, int out_size)
{
    const float* x1 = (const float*)d_in[0];
    const float* x2 = (const float*)d_in[1];
    const int* fb   = (const int*)d_in[2];
    float* out      = (float*)d_out;

    const int B = in_sizes[2] / 5;      // flip_bits is (5, B)

    dim3 block(256, 1, 1);
    dim3 grid(128 / 32, 128 / 32, B * 128);

    shuffleAug_kernel<<<grid, block>>>(x1, x2, fb, out, B);
}

// round 3
// speedup vs baseline: 1.1739x; 1.1029x over previous
#include <cuda_runtime.h>

// shuffleAug: per-sample dihedral transform of two (B,64,128,128) fp32 tensors.
//   if f2 (swap):  src_i = flip_{f0^f4}(j), src_j = flip_{f1^f3}(i)
//   else:          src_i = flip_{f0^f3}(i), src_j = flip_{f1^f4}(j)
//
// R3: 4 tiles per block (one 32-row band of a plane), loads front-batched for
// MLP=4. Non-swap: pure float4 streaming. Swap: 4 padded smem tiles,
// conflict-free scatter/gather.

#define HH 128
#define HWSZ (128 * 128)

__global__ void __launch_bounds__(256) shuffleAug_kernel(
    const float* __restrict__ x1,
    const float* __restrict__ x2,
    const int* __restrict__ fb,   // (5, B) int32
    float* __restrict__ out,
    int B)
{
    __shared__ float tile[4][32][33];

    const int plane = blockIdx.y;       // b * 128 + c
    const int b = plane >> 7;
    const int c = plane & 127;

    const int f0 = fb[0 * B + b];
    const int f1 = fb[1 * B + b];
    const int sw = fb[2 * B + b];
    const int f3 = fb[3 * B + b];
    const int f4 = fb[4 * B + b];

    const int fi = sw ? (f0 ^ f4) : (f0 ^ f3);
    const int fj = sw ? (f1 ^ f3) : (f1 ^ f4);

    const float* src;
    float* dst;
    if (c < 64) {
        src = x1 + ((size_t)b * 64 + c) * HWSZ;
        dst = out + ((size_t)b * 64 + c) * HWSZ;
    } else {
        src = x2 + ((size_t)b * 64 + (c - 64)) * HWSZ;
        dst = out + (size_t)B * 64 * HWSZ + ((size_t)b * 64 + (c - 64)) * HWSZ;
    }

    const int tid = threadIdx.x;        // 0..255
    const int lr  = tid >> 3;           // 0..31  row within tile
    const int lg  = tid & 7;            // 0..7   float4 group within row

    const int i0 = blockIdx.x * 32;     // output band: rows i0..i0+31, all cols
    // tile k covers output cols j0k = 32*k

    if (!sw) {
        // ---- no transpose: 4 independent float4 copies per thread ----
        const int r  = i0 + lr;
        const int sr = fi ? (HH - 1) - r : r;
        const float* srow = src + (size_t)sr * HH;
        float4 v[4];
        if (!fj) {
            #pragma unroll
            for (int k = 0; k < 4; k++)
                v[k] = *(const float4*)(srow + 32 * k + 4 * lg);
        } else {
            #pragma unroll
            for (int k = 0; k < 4; k++) {
                float4 t = *(const float4*)(srow + (HH - 4) - 32 * k - 4 * lg);
                v[k].x = t.w; v[k].y = t.z; v[k].z = t.y; v[k].w = t.x;
            }
        }
        float* drow = dst + (size_t)r * HH;
        #pragma unroll
        for (int k = 0; k < 4; k++)
            *(float4*)(drow + 32 * k + 4 * lg) = v[k];
    } else {
        // ---- transpose path: 4 smem tiles, loads front-batched ----
        float4 v[4];
        #pragma unroll
        for (int k = 0; k < 4; k++) {
            const int j0 = 32 * k;
            const int si0 = fi ? (HH - 32) - j0 : j0;   // source rows cover u=j
            const int sj0 = fj ? (HH - 32) - i0 : i0;   // source cols cover v=i
            v[k] = *(const float4*)(src + (size_t)(si0 + lr) * HH + sj0 + 4 * lg);
        }
        #pragma unroll
        for (int k = 0; k < 4; k++) {
            tile[k][lr][4 * lg + 0] = v[k].x;
            tile[k][lr][4 * lg + 1] = v[k].y;
            tile[k][lr][4 * lg + 2] = v[k].z;
            tile[k][lr][4 * lg + 3] = v[k].w;
        }
        __syncthreads();

        // gather: out(i,j) <- tile row fi?31-jl:jl, col fj?31-il:il
        const int scol = fj ? 31 - lr : lr;
        const int jl0  = 4 * lg;
        const int r0   = fi ? 31 - jl0 : jl0;
        const int st   = fi ? -1 : 1;
        float4 w[4];
        #pragma unroll
        for (int k = 0; k < 4; k++) {
            w[k].x = tile[k][r0         ][scol];
            w[k].y = tile[k][r0 + st    ][scol];
            w[k].z = tile[k][r0 + 2 * st][scol];
            w[k].w = tile[k][r0 + 3 * st][scol];
        }
        float* drow = dst + (size_t)(i0 + lr) * HH;
        #pragma unroll
        for (int k = 0; k < 4; k++)
            *(float4*)(drow + 32 * k + 4 * lg) = w[k];
    }
}

extern "C" void kernel_launch(void* const* d_in, const int* in_sizes, int n_in,
                              void* d_out, int out_size)
{
    const float* x1 = (const float*)d_in[0];
    const float* x2 = (const float*)d_in[1];
    const int* fb   = (const int*)d_in[2];
    float* out      = (float*)d_out;

    const int B = in_sizes[2] / 5;      // flip_bits is (5, B)

    dim3 block(256, 1, 1);
    dim3 grid(128 / 32, B * 128, 1);    // 4 bands x 4096 planes = 16384 blocks

    shuffleAug_kernel<<<grid, block>>>(x1, x2, fb, out, B);
}